// round 10
// baseline (speedup 1.0000x reference)
#include <cuda_runtime.h>
#include <cuda_bf16.h>
#include <cuda_fp16.h>
#include <math.h>
#include <stdint.h>

#define NN 512
#define CC 256
#define HWP 196          // 14*14
#define KTOT 2304        // C*9

// ---------------- scratch (static device globals; no allocation) -------------
// reordered fp16 hi/lo weights: [oc][k'] with k' = (c/16)*144 + kk*16 + (c%16)
__device__ __half g_Whc[CC * KTOT], g_Wlc[CC * KTOT];
__device__ __half g_Wht[CC * KTOT], g_Wlt[CC * KTOT];
__device__ __half g_Whf[CC * KTOT], g_Wlf[CC * KTOT];
__device__ float g_branch[NN * CC * HWP]; // branch conv output (103MB)
__device__ int   g_members[NN * NN];
__device__ int   g_cnt[NN];
__device__ float g_inv[NN];

#define MMA_F16(C, A, B)                                                       \
    asm volatile("mma.sync.aligned.m16n8k16.row.col.f32.f16.f16.f32 "          \
                 "{%0,%1,%2,%3}, {%4,%5,%6,%7}, {%8,%9}, {%0,%1,%2,%3};"       \
                 : "+f"((C)[0]), "+f"((C)[1]), "+f"((C)[2]), "+f"((C)[3])      \
                 : "r"((A)[0]), "r"((A)[1]), "r"((A)[2]), "r"((A)[3]),         \
                   "r"((B)[0]), "r"((B)[1]))

// ---------------- 1) box overlap mask / member lists -------------------------
__global__ void mask_kernel(const float* __restrict__ boxes) {
    int i = blockIdx.x * blockDim.x + threadIdx.x;
    if (i >= NN) return;
    float ax0 = boxes[i * 4 + 0], ay0 = boxes[i * 4 + 1];
    float ax1 = boxes[i * 4 + 2], ay1 = boxes[i * 4 + 3];
    int c = 0;
    for (int j = 0; j < NN; j++) {
        float bx0 = boxes[j * 4 + 0], by0 = boxes[j * 4 + 1];
        float bx1 = boxes[j * 4 + 2], by1 = boxes[j * 4 + 3];
        float ltx = fmaxf(ax0, bx0), lty = fmaxf(ay0, by0);
        float rbx = fminf(ax1, bx1), rby = fminf(ay1, by1);
        float w = fmaxf(rbx - ltx, 0.0f);
        float h = fmaxf(rby - lty, 0.0f);
        float inter = w * h;
        float areaj = (bx1 - bx0) * (by1 - by0);
        if (inter / areaj > 0.9f) { g_members[i * NN + c] = j; c++; }
    }
    g_cnt[i] = c;
    g_inv[i] = 1.0f / (float)c;
}

// ---------------- 2) fold conv1x1 into conv3x3, split fp16 hi/lo, reorder K ---
__global__ void combine_kernel(const float* __restrict__ Wc3, const float* __restrict__ Wc1,
                               const float* __restrict__ Wt3, const float* __restrict__ Wt1,
                               const float* __restrict__ Wf3, const float* __restrict__ Wf1) {
    const float *W3, *W1;
    __half *Wh, *Wl;
    if (blockIdx.z == 0)      { W3 = Wc3; W1 = Wc1; Wh = g_Whc; Wl = g_Wlc; }
    else if (blockIdx.z == 1) { W3 = Wt3; W1 = Wt1; Wh = g_Wht; Wl = g_Wlt; }
    else                      { W3 = Wf3; W1 = Wf1; Wh = g_Whf; Wl = g_Wlf; }

    int ckb = blockIdx.x * 32;
    int ob  = blockIdx.y * 64;
    int tid = threadIdx.x;
    int ck_l = tid >> 3;
    int og   = tid & 7;

    __shared__ __align__(16) float As[32 * 32];
    __shared__ __align__(16) float Bs[32 * 64];

    float acc[8];
#pragma unroll
    for (int j = 0; j < 8; j++) acc[j] = 0.0f;

    for (int mb = 0; mb < 256; mb += 32) {
        __syncthreads();
        for (int idx = tid; idx < 1024; idx += 256) {
            int m = idx >> 5, ck = idx & 31;
            As[idx] = W3[(mb + m) * KTOT + ckb + ck];
        }
        {
            int o  = tid & 63;
            int m8 = (tid >> 6) * 8;
#pragma unroll
            for (int mi = 0; mi < 8; mi++)
                Bs[(m8 + mi) * 64 + o] = W1[(ob + o) * 256 + mb + m8 + mi];
        }
        __syncthreads();
#pragma unroll
        for (int m = 0; m < 32; m++) {
            float a = As[m * 32 + ck_l];
            float b[8];
            *(float4*)&b[0] = *(const float4*)&Bs[m * 64 + og * 8];
            *(float4*)&b[4] = *(const float4*)&Bs[m * 64 + og * 8 + 4];
#pragma unroll
            for (int j = 0; j < 8; j++) acc[j] = fmaf(a, b[j], acc[j]);
        }
    }
    int ck = ckb + ck_l;
    int c = ck / 9, kk = ck % 9;
    int ckp = (c >> 4) * 144 + kk * 16 + (c & 15);
#pragma unroll
    for (int j = 0; j < 8; j++) {
        int oc = ob + og * 8 + j;
        float w = acc[j];
        __half h = __float2half(w);
        __half l = __float2half(w - __half2float(h));
        Wh[oc * KTOT + ckp] = h;
        Wl[oc * KTOT + ckp] = l;
    }
}

// ---------------- 3) conv3x3 as implicit-im2col GEMM on tensor cores ---------
// Role-swapped MMA: A = weights (m16 = oc, LDG.32 fragments from reordered W),
// B = im2col x (n8 = padded positions, 2 conflict-free LDS.32 per tile).
// CTA tile: 128 oc x 224 padded positions (16-wide grid; cols 14,15 discarded).
// 16 warps: wOc = warp&3 (32 oc = 2 m16-tiles), wPos = warp>>2 (56 pos = 7 n8).
// Per warp-kstep: 14 LDS.32 + 16 LDG.32 (prefetched) + 28 MMA.
template <int MODE>
__global__ void __launch_bounds__(512, 1)
conv_mma(const float* __restrict__ x, const float* __restrict__ gc,
         const int* __restrict__ classes,
         const float* __restrict__ bn_gamma, const float* __restrict__ bn_beta,
         const float* __restrict__ bn_mean,  const float* __restrict__ bn_var,
         float* __restrict__ out) {
    const int n  = blockIdx.y;
    const int ob = blockIdx.x * 128;
    const int tid = threadIdx.x;
    const int lane = tid & 31;
    const int warp = tid >> 5;
    const int wOc  = warp & 3;
    const int wPos = warp >> 2;
    const int xbase = n * CC * HWP;

    const __half *Wh, *Wl;
    bool gather = false;
    int mcount = 1;
    float invn = 1.0f;
    if (MODE == 0) {
        if (classes[n] != 0) { Wh = g_Whc; Wl = g_Wlc; }
        else {
            Wh = g_Wht; Wl = g_Wlt;
            int c = g_cnt[n];
            if (c > 1) { gather = true; mcount = c; invn = g_inv[n]; }
        }
    } else { Wh = g_Whf; Wl = g_Wlf; }

    // Xs: 288 padded rows (18x16 spatial) x 16 channels, row stride 24 halves (48B)
    __shared__ __align__(16) __half Xs[2][288 * 24];

    // A row-base pointers (this thread's oc row + k-pair column)
    const int ocw = ob + wOc * 32 + (lane >> 2);
    const __half* pH = Wh + (size_t)ocw * KTOT + 2 * (lane & 3);
    const __half* pL = Wl + (size_t)ocw * KTOT + 2 * (lane & 3);

    // B smem byte base: position row (n0 + lane>>2), channel word (lane&3)
    const int n0 = wPos * 56;
    const uint32_t brow = (uint32_t)(n0 + (lane >> 2)) * 48 + 4 * (lane & 3);

    float acc[7][2][4];
#pragma unroll
    for (int i = 0; i < 7; i++)
#pragma unroll
        for (int t = 0; t < 2; t++)
#pragma unroll
            for (int v = 0; v < 4; v++) acc[i][t][v] = 0.0f;

    // ---- per-warp chunk loader: warp w handles channel w of the chunk ----
    float vstage[9];
    auto load_vals = [&](int ch16) {
        int cglob = ch16 * 16 + warp;
        int cb = xbase + cglob * HWP;
#pragma unroll
        for (int rep = 0; rep < 9; rep++) {
            int pr = rep * 32 + lane;       // 0..287 over 18x16 padded tile
            int iy = pr >> 4, ix = pr & 15;
            float v = 0.0f;
            if (iy >= 1 && iy < 15 && ix >= 1 && ix < 15) {
                int off = (iy - 1) * 14 + (ix - 1);
                if (MODE == 0) {
                    if (!gather) v = x[cb + off];
                    else {
                        float s = 0.0f;
                        for (int t = 0; t < mcount; t++)
                            s += x[g_members[n * NN + t] * CC * HWP + cglob * HWP + off];
                        v = s * invn;
                    }
                } else {
                    int gi = cb + off;
                    v = g_branch[gi] + x[gi] + gc[gi];
                }
            }
            vstage[rep] = v;
        }
    };
    auto store_vals = [&](int buf) {
#pragma unroll
        for (int rep = 0; rep < 9; rep++) {
            int pr = rep * 32 + lane;
            Xs[buf][pr * 24 + warp] = __float2half(vstage[rep]);
        }
    };

#define LDA4(dst, base, ko)                                                    \
    do {                                                                       \
        (dst)[0] = *(const uint32_t*)((base) + (ko));                          \
        (dst)[1] = *(const uint32_t*)((base) + 8 * KTOT + (ko));               \
        (dst)[2] = *(const uint32_t*)((base) + (ko) + 8);                      \
        (dst)[3] = *(const uint32_t*)((base) + 8 * KTOT + (ko) + 8);           \
    } while (0)

    load_vals(0);
    store_vals(0);
    __syncthreads();

    for (int ch16 = 0; ch16 < 16; ch16++) {
        const int buf = ch16 & 1;
        const char* xb = (const char*)Xs[buf];

        if (ch16 < 15) load_vals(ch16 + 1);   // LDGs in flight under the MMAs

        const int kg = ch16 * 144;
        uint32_t paH[2][4], paL[2][4];
        LDA4(paH[0], pH, kg);
        LDA4(paH[1], pH + 16 * KTOT, kg);
        LDA4(paL[0], pL, kg);
        LDA4(paL[1], pL + 16 * KTOT, kg);

#pragma unroll
        for (int kk = 0; kk < 9; kk++) {
            uint32_t aH[2][4], aL[2][4];
#pragma unroll
            for (int t = 0; t < 2; t++)
#pragma unroll
                for (int v = 0; v < 4; v++) { aH[t][v] = paH[t][v]; aL[t][v] = paL[t][v]; }
            if (kk < 8) {
                int kg2 = kg + (kk + 1) * 16;
                LDA4(paH[0], pH, kg2);
                LDA4(paH[1], pH + 16 * KTOT, kg2);
                LDA4(paL[0], pL, kg2);
                LDA4(paL[1], pL + 16 * KTOT, kg2);
            }
            const uint32_t koffb = brow + (uint32_t)((kk / 3) * 16 + (kk % 3)) * 48;
#pragma unroll
            for (int i = 0; i < 7; i++) {
                uint32_t b[2];
                b[0] = *(const uint32_t*)(xb + koffb + i * 384);
                b[1] = *(const uint32_t*)(xb + koffb + i * 384 + 16);
#pragma unroll
                for (int t = 0; t < 2; t++) {
                    MMA_F16(acc[i][t], aH[t], b);
                    MMA_F16(acc[i][t], aL[t], b);
                }
            }
        }

        if (ch16 < 15) store_vals(buf ^ 1);
        __syncthreads();
    }

    // ---- epilogue: D rows = oc, cols = padded positions ----
    const int px = 2 * (lane & 3);
    if (MODE == 0) {
#pragma unroll
        for (int i = 0; i < 7; i++) {
            int np = n0 + i * 8 + px;
            int xcol = np & 15;
            if (xcol < 14) {
                int pos = (np >> 4) * 14 + xcol;
#pragma unroll
                for (int t = 0; t < 2; t++) {
                    int oc0 = ob + wOc * 32 + t * 16 + (lane >> 2);
                    float* p = &g_branch[xbase + oc0 * HWP + pos];
                    *(float2*)p             = make_float2(acc[i][t][0], acc[i][t][1]);
                    *(float2*)(p + 8 * HWP) = make_float2(acc[i][t][2], acc[i][t][3]);
                }
            }
        }
    } else {
        float sc[2][2], sh[2][2];
#pragma unroll
        for (int t = 0; t < 2; t++) {
#pragma unroll
            for (int r = 0; r < 2; r++) {
                int oc = ob + wOc * 32 + t * 16 + (lane >> 2) + r * 8;
                float s = bn_gamma[oc] * rsqrtf(bn_var[oc] + 1e-5f);
                sc[t][r] = s;
                sh[t][r] = bn_beta[oc] - bn_mean[oc] * s;
            }
        }
#pragma unroll
        for (int i = 0; i < 7; i++) {
            int np = n0 + i * 8 + px;
            int xcol = np & 15;
            if (xcol < 14) {
                int pos = (np >> 4) * 14 + xcol;
#pragma unroll
                for (int t = 0; t < 2; t++) {
                    int oc0 = ob + wOc * 32 + t * 16 + (lane >> 2);
                    float* p = &out[xbase + oc0 * HWP + pos];
                    float v0 = fmaxf(fmaf(acc[i][t][0], sc[t][0], sh[t][0]), 0.0f);
                    float v1 = fmaxf(fmaf(acc[i][t][1], sc[t][0], sh[t][0]), 0.0f);
                    float v2 = fmaxf(fmaf(acc[i][t][2], sc[t][1], sh[t][1]), 0.0f);
                    float v3 = fmaxf(fmaf(acc[i][t][3], sc[t][1], sh[t][1]), 0.0f);
                    *(float2*)p             = make_float2(v0, v1);
                    *(float2*)(p + 8 * HWP) = make_float2(v2, v3);
                }
            }
        }
    }
#undef LDA4
}

// ---------------- launch ------------------------------------------------------
extern "C" void kernel_launch(void* const* d_in, const int* in_sizes, int n_in,
                              void* d_out, int out_size) {
    const float* x       = (const float*)d_in[0];
    const float* gc      = (const float*)d_in[1];
    const float* boxes   = (const float*)d_in[2];
    const int*   classes = (const int*)  d_in[3];
    const float* Wc3     = (const float*)d_in[4];
    const float* Wc1     = (const float*)d_in[5];
    const float* Wt3     = (const float*)d_in[6];
    const float* Wt1     = (const float*)d_in[7];
    const float* Wf3     = (const float*)d_in[8];
    const float* Wf1     = (const float*)d_in[9];
    const float* bg      = (const float*)d_in[10];
    const float* bb      = (const float*)d_in[11];
    const float* bm      = (const float*)d_in[12];
    const float* bv      = (const float*)d_in[13];
    float* out = (float*)d_out;

    mask_kernel<<<2, 256>>>(boxes);
    combine_kernel<<<dim3(72, 4, 3), 256>>>(Wc3, Wc1, Wt3, Wt1, Wf3, Wf1);
    conv_mma<0><<<dim3(2, NN), 512>>>(x, gc, classes, bg, bb, bm, bv, nullptr);
    conv_mma<1><<<dim3(2, NN), 512>>>(x, gc, classes, bg, bb, bm, bv, out);
}

// round 12
// speedup vs baseline: 2.5816x; 2.5816x over previous
#include <cuda_runtime.h>
#include <cuda_bf16.h>
#include <cuda_fp16.h>
#include <math.h>
#include <stdint.h>

#define NN 512
#define CC 256
#define HWP 196          // 14*14
#define KTOT 2304        // C*9

// dynamic smem layout (halves):
#define XS_STRIDE 24                 // 48B row stride: 16B-aligned for ldmatrix,
                                     // banks 12p mod 32 -> conflict-free
#define XS_SIZE   (288 * XS_STRIDE)  // one x buffer (18x16 spatial x 16 ch)
#define WS_STRIDE 152                // 304B oc-row stride: 16B-multiple, 12r banks
#define WS_SLICE  (128 * WS_STRIDE)  // one h-or-l slice (128 oc x 144 k + pad)
#define WS_BUF    (2 * WS_SLICE)     // hi + lo
#define XS_OFF    0
#define WS_OFF    (2 * XS_SIZE)
#define SMEM_HALVES (2 * XS_SIZE + 2 * WS_BUF)
#define SMEM_BYTES  (SMEM_HALVES * 2)

// ---------------- scratch (static device globals; no allocation) -------------
// reordered fp16 hi/lo weights: [oc][k'] with k' = (c/16)*144 + kk*16 + (c%16)
__device__ __align__(256) __half g_Whc[CC * KTOT], g_Wlc[CC * KTOT];
__device__ __align__(256) __half g_Wht[CC * KTOT], g_Wlt[CC * KTOT];
__device__ __align__(256) __half g_Whf[CC * KTOT], g_Wlf[CC * KTOT];
__device__ float g_branch[NN * CC * HWP]; // branch conv output (103MB)
__device__ int   g_members[NN * NN];
__device__ int   g_cnt[NN];
__device__ float g_inv[NN];

__device__ __forceinline__ uint32_t s2u(const void* p) {
    uint32_t a;
    asm("{ .reg .u64 t; cvta.to.shared.u64 t, %1; cvt.u32.u64 %0, t; }"
        : "=r"(a) : "l"(p));
    return a;
}

#define MMA_F16(C, A, B0, B1)                                                  \
    asm volatile("mma.sync.aligned.m16n8k16.row.col.f32.f16.f16.f32 "          \
                 "{%0,%1,%2,%3}, {%4,%5,%6,%7}, {%8,%9}, {%0,%1,%2,%3};"       \
                 : "+f"((C)[0]), "+f"((C)[1]), "+f"((C)[2]), "+f"((C)[3])      \
                 : "r"((A)[0]), "r"((A)[1]), "r"((A)[2]), "r"((A)[3]),         \
                   "r"(B0), "r"(B1))

#define LDMATRIX_X4(A, addr)                                                   \
    asm volatile("ldmatrix.sync.aligned.m8n8.x4.shared.b16 {%0,%1,%2,%3}, [%4];" \
                 : "=r"((A)[0]), "=r"((A)[1]), "=r"((A)[2]), "=r"((A)[3])      \
                 : "r"(addr))

#define CP_ASYNC16(dst, src)                                                   \
    asm volatile("cp.async.cg.shared.global [%0], [%1], 16;" :: "r"(dst), "l"(src))
#define CP_COMMIT()  asm volatile("cp.async.commit_group;")
#define CP_WAIT0()   asm volatile("cp.async.wait_group 0;" ::: "memory")

// ---------------- 1) box overlap mask / member lists -------------------------
__global__ void mask_kernel(const float* __restrict__ boxes) {
    int i = blockIdx.x * blockDim.x + threadIdx.x;
    if (i >= NN) return;
    float ax0 = boxes[i * 4 + 0], ay0 = boxes[i * 4 + 1];
    float ax1 = boxes[i * 4 + 2], ay1 = boxes[i * 4 + 3];
    int c = 0;
    for (int j = 0; j < NN; j++) {
        float bx0 = boxes[j * 4 + 0], by0 = boxes[j * 4 + 1];
        float bx1 = boxes[j * 4 + 2], by1 = boxes[j * 4 + 3];
        float ltx = fmaxf(ax0, bx0), lty = fmaxf(ay0, by0);
        float rbx = fminf(ax1, bx1), rby = fminf(ay1, by1);
        float w = fmaxf(rbx - ltx, 0.0f);
        float h = fmaxf(rby - lty, 0.0f);
        float inter = w * h;
        float areaj = (bx1 - bx0) * (by1 - by0);
        if (inter / areaj > 0.9f) { g_members[i * NN + c] = j; c++; }
    }
    g_cnt[i] = c;
    g_inv[i] = 1.0f / (float)c;
}

// ---------------- 2) fold conv1x1 into conv3x3, split fp16 hi/lo, reorder K ---
__global__ void combine_kernel(const float* __restrict__ Wc3, const float* __restrict__ Wc1,
                               const float* __restrict__ Wt3, const float* __restrict__ Wt1,
                               const float* __restrict__ Wf3, const float* __restrict__ Wf1) {
    const float *W3, *W1;
    __half *Wh, *Wl;
    if (blockIdx.z == 0)      { W3 = Wc3; W1 = Wc1; Wh = g_Whc; Wl = g_Wlc; }
    else if (blockIdx.z == 1) { W3 = Wt3; W1 = Wt1; Wh = g_Wht; Wl = g_Wlt; }
    else                      { W3 = Wf3; W1 = Wf1; Wh = g_Whf; Wl = g_Wlf; }

    int ckb = blockIdx.x * 32;
    int ob  = blockIdx.y * 64;
    int tid = threadIdx.x;
    int ck_l = tid >> 3;
    int og   = tid & 7;

    __shared__ __align__(16) float As[32 * 32];
    __shared__ __align__(16) float Bs[32 * 64];

    float acc[8];
#pragma unroll
    for (int j = 0; j < 8; j++) acc[j] = 0.0f;

    for (int mb = 0; mb < 256; mb += 32) {
        __syncthreads();
        for (int idx = tid; idx < 1024; idx += 256) {
            int m = idx >> 5, ck = idx & 31;
            As[idx] = W3[(mb + m) * KTOT + ckb + ck];
        }
        {
            int o  = tid & 63;
            int m8 = (tid >> 6) * 8;
#pragma unroll
            for (int mi = 0; mi < 8; mi++)
                Bs[(m8 + mi) * 64 + o] = W1[(ob + o) * 256 + mb + m8 + mi];
        }
        __syncthreads();
#pragma unroll
        for (int m = 0; m < 32; m++) {
            float a = As[m * 32 + ck_l];
            float b[8];
            *(float4*)&b[0] = *(const float4*)&Bs[m * 64 + og * 8];
            *(float4*)&b[4] = *(const float4*)&Bs[m * 64 + og * 8 + 4];
#pragma unroll
            for (int j = 0; j < 8; j++) acc[j] = fmaf(a, b[j], acc[j]);
        }
    }
    int ck = ckb + ck_l;
    int c = ck / 9, kk = ck % 9;
    int ckp = (c >> 4) * 144 + kk * 16 + (c & 15);
#pragma unroll
    for (int j = 0; j < 8; j++) {
        int oc = ob + og * 8 + j;
        float w = acc[j];
        __half h = __float2half(w);
        __half l = __float2half(w - __half2float(h));
        Wh[oc * KTOT + ckp] = h;
        Wl[oc * KTOT + ckp] = l;
    }
}

// ---------------- 3) conv3x3 as implicit-im2col GEMM on tensor cores ---------
// A = x (m16 = pos, ldmatrix from Xs, 48B stride), B = weights (n8 = oc,
// ldmatrix from per-chunk smem-staged slice; cp.async double-buffered).
// CTA: 128 oc x 224 padded pos. 16 warps: wM=warp&1 (112 pos), wN=warp>>1 (16 oc).
// Per warp-kstep: 7 A-ldmatrix.x4 (28 wf) + 2 B-ldmatrix.x4 (8 wf) + 28 MMA.
template <int MODE>
__global__ void __launch_bounds__(512, 1)
conv_mma(const float* __restrict__ x, const float* __restrict__ gc,
         const int* __restrict__ classes,
         const float* __restrict__ bn_gamma, const float* __restrict__ bn_beta,
         const float* __restrict__ bn_mean,  const float* __restrict__ bn_var,
         float* __restrict__ out) {
    extern __shared__ __align__(16) __half dsm[];
    const int n  = blockIdx.y;
    const int ob = blockIdx.x * 128;
    const int tid = threadIdx.x;
    const int lane = tid & 31;
    const int warp = tid >> 5;
    const int wM = warp & 1;
    const int wN = warp >> 1;
    const int xbase = n * CC * HWP;

    const __half *Wh, *Wl;
    bool gather = false;
    int mcount = 1;
    float invn = 1.0f;
    if (MODE == 0) {
        if (classes[n] != 0) { Wh = g_Whc; Wl = g_Wlc; }
        else {
            Wh = g_Wht; Wl = g_Wlt;
            int c = g_cnt[n];
            if (c > 1) { gather = true; mcount = c; invn = g_inv[n]; }
        }
    } else { Wh = g_Whf; Wl = g_Wlf; }

    __half* Xs = dsm + XS_OFF;           // [2][288 * XS_STRIDE]
    __half* Wsm = dsm + WS_OFF;          // [2][2][128 * WS_STRIDE]
    const uint32_t xs_base = s2u(Xs);
    const uint32_t ws_base = s2u(Wsm);

    // A-tile row bases (lane&15 -> pos row in 18x16 padded grid)
    int pb[7];
#pragma unroll
    for (int i = 0; i < 7; i++) {
        int m = wM * 112 + i * 16 + (lane & 15);
        pb[i] = (m / 14) * 16 + (m % 14);
    }
    const uint32_t a_half = (uint32_t)(lane >> 4) * 16;   // +16B for k8-15 lanes

    // B ldmatrix per-lane address parts: mi = lane>>3 -> matrix
    //   row = wN*16 + (mi>>1)*8 + (lane&7), col byte = kk*32 + (mi&1)*16
    const int bmi = lane >> 3;
    const uint32_t b_row_off =
        (uint32_t)(wN * 16 + ((bmi >> 1) << 3) + (lane & 7)) * (WS_STRIDE * 2);
    const uint32_t b_col16 = (uint32_t)(bmi & 1) * 16;

    float acc[7][2][4];
#pragma unroll
    for (int i = 0; i < 7; i++)
#pragma unroll
        for (int t = 0; t < 2; t++)
#pragma unroll
            for (int v = 0; v < 4; v++) acc[i][t][v] = 0.0f;

    // ---- x chunk loader: warp w handles channel w ----
    float vstage[9];
    auto load_vals = [&](int ch16) {
        int cglob = ch16 * 16 + warp;
        int cb = xbase + cglob * HWP;
#pragma unroll
        for (int rep = 0; rep < 9; rep++) {
            int pr = rep * 32 + lane;       // 0..287 over 18x16 padded tile
            int iy = pr >> 4, ix = pr & 15;
            float v = 0.0f;
            if (iy >= 1 && iy < 15 && ix >= 1 && ix < 15) {
                int off = (iy - 1) * 14 + (ix - 1);
                if (MODE == 0) {
                    if (!gather) v = x[cb + off];
                    else {
                        float s = 0.0f;
                        for (int t = 0; t < mcount; t++)
                            s += x[g_members[n * NN + t] * CC * HWP + cglob * HWP + off];
                        v = s * invn;
                    }
                } else {
                    int gi = cb + off;
                    v = g_branch[gi] + x[gi] + gc[gi];
                }
            }
            vstage[rep] = v;
        }
    };
    auto store_vals = [&](int buf) {
        __half* xd = Xs + buf * XS_SIZE;
#pragma unroll
        for (int rep = 0; rep < 9; rep++) {
            int pr = rep * 32 + lane;
            xd[pr * XS_STRIDE + warp] = __float2half(vstage[rep]);
        }
    };

    // ---- W chunk stager: 4608 x 16B cp.async (hi 2304 + lo 2304), 9/thread ----
    auto stage_w = [&](int ch16, int buf) {
        uint32_t dbase = ws_base + (uint32_t)buf * (WS_BUF * 2);
#pragma unroll
        for (int it = 0; it < 9; it++) {
            int idx = it * 512 + tid;        // 0..4607
            int s   = idx / 2304;            // 0 = hi, 1 = lo
            int rem = idx - s * 2304;
            int r   = rem / 18;              // oc row 0..127
            int c8  = rem - r * 18;          // 16B col 0..17
            const __half* src = (s ? Wl : Wh) +
                (size_t)(ob + r) * KTOT + ch16 * 144 + c8 * 8;
            uint32_t dst = dbase + (uint32_t)(s * WS_SLICE + r * WS_STRIDE + c8 * 8) * 2;
            CP_ASYNC16(dst, src);
        }
    };

    load_vals(0);
    store_vals(0);
    stage_w(0, 0);
    CP_COMMIT();
    CP_WAIT0();
    __syncthreads();

    for (int ch16 = 0; ch16 < 16; ch16++) {
        const int buf = ch16 & 1;
        const uint32_t xb = xs_base + (uint32_t)buf * (XS_SIZE * 2);
        const uint32_t wbh = ws_base + (uint32_t)buf * (WS_BUF * 2) + b_row_off + b_col16;
        const uint32_t wbl = wbh + (uint32_t)(WS_SLICE * 2);

        if (ch16 < 15) {
            load_vals(ch16 + 1);             // x LDGs in flight under MMAs
            stage_w(ch16 + 1, buf ^ 1);      // W cp.async in flight under MMAs
            CP_COMMIT();
        }

#pragma unroll
        for (int kk = 0; kk < 9; kk++) {
            uint32_t bh[4], bl[4];
            LDMATRIX_X4(bh, wbh + (uint32_t)kk * 32);
            LDMATRIX_X4(bl, wbl + (uint32_t)kk * 32);
            const int koff = (kk / 3) * 16 + (kk % 3);   // dy*16+dx pos offset
#pragma unroll
            for (int i = 0; i < 7; i++) {
                uint32_t a[4];
                LDMATRIX_X4(a, xb + (uint32_t)(pb[i] + koff) * (XS_STRIDE * 2) + a_half);
                MMA_F16(acc[i][0], a, bh[0], bh[1]);
                MMA_F16(acc[i][0], a, bl[0], bl[1]);
                MMA_F16(acc[i][1], a, bh[2], bh[3]);
                MMA_F16(acc[i][1], a, bl[2], bl[3]);
            }
        }

        if (ch16 < 15) store_vals(buf ^ 1);
        CP_WAIT0();
        __syncthreads();
    }

    // ---- epilogue (m16 = pos, n8 = oc) ----
    if (MODE == 0) {
#pragma unroll
        for (int i = 0; i < 7; i++) {
            int m0 = wM * 112 + i * 16 + (lane >> 2);
#pragma unroll
            for (int t = 0; t < 2; t++) {
                int oc0 = ob + wN * 16 + t * 8 + 2 * (lane & 3);
                float* p = &g_branch[xbase + oc0 * HWP];
                if (m0 < HWP) {
                    p[m0]       = acc[i][t][0];
                    p[HWP + m0] = acc[i][t][1];
                }
                if (m0 + 8 < HWP) {
                    p[m0 + 8]       = acc[i][t][2];
                    p[HWP + m0 + 8] = acc[i][t][3];
                }
            }
        }
    } else {
        float sc[2][2], sh[2][2];
#pragma unroll
        for (int t = 0; t < 2; t++) {
#pragma unroll
            for (int j = 0; j < 2; j++) {
                int oc = ob + wN * 16 + t * 8 + 2 * (lane & 3) + j;
                float s = bn_gamma[oc] * rsqrtf(bn_var[oc] + 1e-5f);
                sc[t][j] = s;
                sh[t][j] = bn_beta[oc] - bn_mean[oc] * s;
            }
        }
#pragma unroll
        for (int i = 0; i < 7; i++) {
            int m0 = wM * 112 + i * 16 + (lane >> 2);
#pragma unroll
            for (int t = 0; t < 2; t++) {
                int oc0 = ob + wN * 16 + t * 8 + 2 * (lane & 3);
                float* p = &out[xbase + oc0 * HWP];
                if (m0 < HWP) {
                    p[m0]       = fmaxf(fmaf(acc[i][t][0], sc[t][0], sh[t][0]), 0.0f);
                    p[HWP + m0] = fmaxf(fmaf(acc[i][t][1], sc[t][1], sh[t][1]), 0.0f);
                }
                if (m0 + 8 < HWP) {
                    p[m0 + 8]       = fmaxf(fmaf(acc[i][t][2], sc[t][0], sh[t][0]), 0.0f);
                    p[HWP + m0 + 8] = fmaxf(fmaf(acc[i][t][3], sc[t][1], sh[t][1]), 0.0f);
                }
            }
        }
    }
}

// ---------------- launch ------------------------------------------------------
extern "C" void kernel_launch(void* const* d_in, const int* in_sizes, int n_in,
                              void* d_out, int out_size) {
    const float* x       = (const float*)d_in[0];
    const float* gc      = (const float*)d_in[1];
    const float* boxes   = (const float*)d_in[2];
    const int*   classes = (const int*)  d_in[3];
    const float* Wc3     = (const float*)d_in[4];
    const float* Wc1     = (const float*)d_in[5];
    const float* Wt3     = (const float*)d_in[6];
    const float* Wt1     = (const float*)d_in[7];
    const float* Wf3     = (const float*)d_in[8];
    const float* Wf1     = (const float*)d_in[9];
    const float* bg      = (const float*)d_in[10];
    const float* bb      = (const float*)d_in[11];
    const float* bm      = (const float*)d_in[12];
    const float* bv      = (const float*)d_in[13];
    float* out = (float*)d_out;

    static bool attr_done = false;
    if (!attr_done) {
        cudaFuncSetAttribute(conv_mma<0>,
            cudaFuncAttributeMaxDynamicSharedMemorySize, SMEM_BYTES);
        cudaFuncSetAttribute(conv_mma<1>,
            cudaFuncAttributeMaxDynamicSharedMemorySize, SMEM_BYTES);
        attr_done = true;
    }

    mask_kernel<<<2, 256>>>(boxes);
    combine_kernel<<<dim3(72, 4, 3), 256>>>(Wc3, Wc1, Wt3, Wt1, Wf3, Wf1);
    conv_mma<0><<<dim3(2, NN), 512, SMEM_BYTES>>>(x, gc, classes, bg, bb, bm, bv, nullptr);
    conv_mma<1><<<dim3(2, NN), 512, SMEM_BYTES>>>(x, gc, classes, bg, bb, bm, bv, out);
}

// round 13
// speedup vs baseline: 3.1394x; 1.2161x over previous
#include <cuda_runtime.h>
#include <cuda_bf16.h>
#include <cuda_fp16.h>
#include <math.h>
#include <stdint.h>

#define NN 512
#define CC 256
#define HWP 196          // 14*14
#define KTOT 2304        // C*9

// dynamic smem layout (halves):
#define XS_STRIDE 24                 // 48B row stride: 16B-aligned for ldmatrix
#define XS_ROWS   160                // 10x16 padded rows (pos-half + halo)
#define XS_SIZE   (XS_ROWS * XS_STRIDE)
#define WS_STRIDE 152                // 304B oc-row stride (144 k + pad)
#define WS_SLICE  (128 * WS_STRIDE)  // single fp16 slice, 128 oc x 144 k
#define XS_OFF    0
#define WS_OFF    (2 * XS_SIZE)
#define SMEM_HALVES (2 * XS_SIZE + 2 * WS_SLICE)
#define SMEM_BYTES  (SMEM_HALVES * 2)   // 93184 B -> 2 CTAs/SM

// ---------------- scratch (static device globals; no allocation) -------------
// reordered fp16 weights: [oc][k'] with k' = (c/16)*144 + kk*16 + (c%16)
__device__ __align__(256) __half g_Wc[CC * KTOT];
__device__ __align__(256) __half g_Wt[CC * KTOT];
__device__ __align__(256) __half g_Wf[CC * KTOT];
__device__ float g_branch[NN * CC * HWP]; // branch conv output (103MB)
__device__ int   g_members[NN * NN];
__device__ int   g_cnt[NN];
__device__ float g_inv[NN];

__device__ __forceinline__ uint32_t s2u(const void* p) {
    uint32_t a;
    asm("{ .reg .u64 t; cvta.to.shared.u64 t, %1; cvt.u32.u64 %0, t; }"
        : "=r"(a) : "l"(p));
    return a;
}

#define MMA_F16(C, A, B0, B1)                                                  \
    asm volatile("mma.sync.aligned.m16n8k16.row.col.f32.f16.f16.f32 "          \
                 "{%0,%1,%2,%3}, {%4,%5,%6,%7}, {%8,%9}, {%0,%1,%2,%3};"       \
                 : "+f"((C)[0]), "+f"((C)[1]), "+f"((C)[2]), "+f"((C)[3])      \
                 : "r"((A)[0]), "r"((A)[1]), "r"((A)[2]), "r"((A)[3]),         \
                   "r"(B0), "r"(B1))

#define LDMATRIX_X4(A, addr)                                                   \
    asm volatile("ldmatrix.sync.aligned.m8n8.x4.shared.b16 {%0,%1,%2,%3}, [%4];" \
                 : "=r"((A)[0]), "=r"((A)[1]), "=r"((A)[2]), "=r"((A)[3])      \
                 : "r"(addr))

#define CP_ASYNC16(dst, src)                                                   \
    asm volatile("cp.async.cg.shared.global [%0], [%1], 16;" :: "r"(dst), "l"(src))
#define CP_COMMIT()  asm volatile("cp.async.commit_group;")
#define CP_WAIT0()   asm volatile("cp.async.wait_group 0;" ::: "memory")

// ---------------- 1) box overlap mask / member lists -------------------------
__global__ void mask_kernel(const float* __restrict__ boxes) {
    int i = blockIdx.x * blockDim.x + threadIdx.x;
    if (i >= NN) return;
    float ax0 = boxes[i * 4 + 0], ay0 = boxes[i * 4 + 1];
    float ax1 = boxes[i * 4 + 2], ay1 = boxes[i * 4 + 3];
    int c = 0;
    for (int j = 0; j < NN; j++) {
        float bx0 = boxes[j * 4 + 0], by0 = boxes[j * 4 + 1];
        float bx1 = boxes[j * 4 + 2], by1 = boxes[j * 4 + 3];
        float ltx = fmaxf(ax0, bx0), lty = fmaxf(ay0, by0);
        float rbx = fminf(ax1, bx1), rby = fminf(ay1, by1);
        float w = fmaxf(rbx - ltx, 0.0f);
        float h = fmaxf(rby - lty, 0.0f);
        float inter = w * h;
        float areaj = (bx1 - bx0) * (by1 - by0);
        if (inter / areaj > 0.9f) { g_members[i * NN + c] = j; c++; }
    }
    g_cnt[i] = c;
    g_inv[i] = 1.0f / (float)c;
}

// ---------------- 2) fold conv1x1 into conv3x3, fp16, reorder K ---------------
__global__ void combine_kernel(const float* __restrict__ Wc3, const float* __restrict__ Wc1,
                               const float* __restrict__ Wt3, const float* __restrict__ Wt1,
                               const float* __restrict__ Wf3, const float* __restrict__ Wf1) {
    const float *W3, *W1;
    __half *Wo;
    if (blockIdx.z == 0)      { W3 = Wc3; W1 = Wc1; Wo = g_Wc; }
    else if (blockIdx.z == 1) { W3 = Wt3; W1 = Wt1; Wo = g_Wt; }
    else                      { W3 = Wf3; W1 = Wf1; Wo = g_Wf; }

    int ckb = blockIdx.x * 32;
    int ob  = blockIdx.y * 64;
    int tid = threadIdx.x;
    int ck_l = tid >> 3;
    int og   = tid & 7;

    __shared__ __align__(16) float As[32 * 32];
    __shared__ __align__(16) float Bs[32 * 64];

    float acc[8];
#pragma unroll
    for (int j = 0; j < 8; j++) acc[j] = 0.0f;

    for (int mb = 0; mb < 256; mb += 32) {
        __syncthreads();
        for (int idx = tid; idx < 1024; idx += 256) {
            int m = idx >> 5, ck = idx & 31;
            As[idx] = W3[(mb + m) * KTOT + ckb + ck];
        }
        {
            int o  = tid & 63;
            int m8 = (tid >> 6) * 8;
#pragma unroll
            for (int mi = 0; mi < 8; mi++)
                Bs[(m8 + mi) * 64 + o] = W1[(ob + o) * 256 + mb + m8 + mi];
        }
        __syncthreads();
#pragma unroll
        for (int m = 0; m < 32; m++) {
            float a = As[m * 32 + ck_l];
            float b[8];
            *(float4*)&b[0] = *(const float4*)&Bs[m * 64 + og * 8];
            *(float4*)&b[4] = *(const float4*)&Bs[m * 64 + og * 8 + 4];
#pragma unroll
            for (int j = 0; j < 8; j++) acc[j] = fmaf(a, b[j], acc[j]);
        }
    }
    int ck = ckb + ck_l;
    int c = ck / 9, kk = ck % 9;
    int ckp = (c >> 4) * 144 + kk * 16 + (c & 15);
#pragma unroll
    for (int j = 0; j < 8; j++) {
        int oc = ob + og * 8 + j;
        Wo[oc * KTOT + ckp] = __float2half(acc[j]);
    }
}

// ---------------- 3) conv3x3 as implicit-im2col GEMM on tensor cores ---------
// 256-thread CTA = 112 pos (one pos-half) x 128 oc; grid (4, 512):
//   blockIdx.x bit0 = oc half, bit1 = pos half. 2 CTAs/SM (91KB smem each)
//   -> decoupled barrier domains overlap fill and MMA phases across CTAs.
// 8 warps, all on the same 112 pos; warp covers 16 oc (2 n8 tiles).
// A = x (ldmatrix from half-tile Xs, 10x16 rows + halo), B = fp16 W
// (ldmatrix from cp.async-staged slice). Per warp-kstep: 7 A-x4 + 1 B-x4 + 14 MMA.
template <int MODE>
__global__ void __launch_bounds__(256, 2)
conv_mma(const float* __restrict__ x, const float* __restrict__ gc,
         const int* __restrict__ classes,
         const float* __restrict__ bn_gamma, const float* __restrict__ bn_beta,
         const float* __restrict__ bn_mean,  const float* __restrict__ bn_var,
         float* __restrict__ out) {
    extern __shared__ __align__(16) __half dsm[];
    const int n   = blockIdx.y;
    const int ocb = (blockIdx.x & 1) * 128;
    const int wMb = blockIdx.x >> 1;       // pos half
    const int ry0 = wMb * 8;               // first padded input row of this half
    const int tid = threadIdx.x;
    const int lane = tid & 31;
    const int warp = tid >> 5;
    const int xbase = n * CC * HWP;

    const __half* Wg;
    bool gather = false;
    int mcount = 1;
    float invn = 1.0f;
    if (MODE == 0) {
        if (classes[n] != 0) { Wg = g_Wc; }
        else {
            Wg = g_Wt;
            int c = g_cnt[n];
            if (c > 1) { gather = true; mcount = c; invn = g_inv[n]; }
        }
    } else { Wg = g_Wf; }

    __half* Xs  = dsm + XS_OFF;          // [2][XS_ROWS * XS_STRIDE]
    __half* Wsm = dsm + WS_OFF;          // [2][128 * WS_STRIDE]
    const uint32_t xs_base = s2u(Xs);
    const uint32_t ws_base = s2u(Wsm);

    // A-tile row bases in LOCAL Xs coords (this pos-half)
    int pb[7];
#pragma unroll
    for (int i = 0; i < 7; i++) {
        int m = wMb * 112 + i * 16 + (lane & 15);
        pb[i] = (m / 14 - ry0) * 16 + (m % 14);
    }
    const uint32_t a_half = (uint32_t)(lane >> 4) * 16;   // +16B for k8-15 lanes

    // B ldmatrix lane address parts
    const int bmi = lane >> 3;
    const uint32_t b_row_off =
        (uint32_t)(warp * 16 + ((bmi >> 1) << 3) + (lane & 7)) * (WS_STRIDE * 2);
    const uint32_t b_col16 = (uint32_t)(bmi & 1) * 16;

    float acc[7][2][4];
#pragma unroll
    for (int i = 0; i < 7; i++)
#pragma unroll
        for (int t = 0; t < 2; t++)
#pragma unroll
            for (int v = 0; v < 4; v++) acc[i][t][v] = 0.0f;

    // ---- x chunk loader: warp w handles channels 2w, 2w+1 of the chunk ----
    float vstage[2][5];
    auto load_vals = [&](int ch16) {
#pragma unroll
        for (int chi = 0; chi < 2; chi++) {
            int cglob = ch16 * 16 + 2 * warp + chi;
            int cb = xbase + cglob * HWP;
#pragma unroll
            for (int rep = 0; rep < 5; rep++) {
                int pr = rep * 32 + lane;       // 0..159 over local 10x16 tile
                int iy = ry0 + (pr >> 4);
                int ix = pr & 15;
                float v = 0.0f;
                if (iy >= 1 && iy < 15 && ix >= 1 && ix < 15) {
                    int off = (iy - 1) * 14 + (ix - 1);
                    if (MODE == 0) {
                        if (!gather) v = x[cb + off];
                        else {
                            float s = 0.0f;
                            for (int t = 0; t < mcount; t++)
                                s += x[g_members[n * NN + t] * CC * HWP + cglob * HWP + off];
                            v = s * invn;
                        }
                    } else {
                        int gi = cb + off;
                        v = g_branch[gi] + x[gi] + gc[gi];
                    }
                }
                vstage[chi][rep] = v;
            }
        }
    };
    auto store_vals = [&](int buf) {
        __half* xd = Xs + buf * XS_SIZE;
#pragma unroll
        for (int chi = 0; chi < 2; chi++)
#pragma unroll
            for (int rep = 0; rep < 5; rep++) {
                int pr = rep * 32 + lane;
                xd[pr * XS_STRIDE + 2 * warp + chi] = __float2half(vstage[chi][rep]);
            }
    };

    // ---- W chunk stager: 2304 x 16B cp.async, 9/thread ----
    auto stage_w = [&](int ch16, int buf) {
        uint32_t dbase = ws_base + (uint32_t)buf * (WS_SLICE * 2);
#pragma unroll
        for (int it = 0; it < 9; it++) {
            int idx = it * 256 + tid;        // 0..2303
            int r   = idx / 18;              // oc row 0..127
            int c8  = idx - r * 18;          // 16B col 0..17
            const __half* src = Wg + (size_t)(ocb + r) * KTOT + ch16 * 144 + c8 * 8;
            uint32_t dst = dbase + (uint32_t)(r * WS_STRIDE + c8 * 8) * 2;
            CP_ASYNC16(dst, src);
        }
    };

    load_vals(0);
    store_vals(0);
    stage_w(0, 0);
    CP_COMMIT();
    CP_WAIT0();
    __syncthreads();

    for (int ch16 = 0; ch16 < 16; ch16++) {
        const int buf = ch16 & 1;
        const uint32_t xb = xs_base + (uint32_t)buf * (XS_SIZE * 2);
        const uint32_t wb = ws_base + (uint32_t)buf * (WS_SLICE * 2) + b_row_off + b_col16;

        if (ch16 < 15) {
            load_vals(ch16 + 1);             // x LDGs in flight under MMAs
            stage_w(ch16 + 1, buf ^ 1);      // W cp.async in flight under MMAs
            CP_COMMIT();
        }

#pragma unroll
        for (int kk = 0; kk < 9; kk++) {
            uint32_t bh[4];
            LDMATRIX_X4(bh, wb + (uint32_t)kk * 32);
            const int koff = (kk / 3) * 16 + (kk % 3);   // dy*16+dx pos offset
#pragma unroll
            for (int i = 0; i < 7; i++) {
                uint32_t a[4];
                LDMATRIX_X4(a, xb + (uint32_t)(pb[i] + koff) * (XS_STRIDE * 2) + a_half);
                MMA_F16(acc[i][0], a, bh[0], bh[1]);
                MMA_F16(acc[i][1], a, bh[2], bh[3]);
            }
        }

        if (ch16 < 15) store_vals(buf ^ 1);
        CP_WAIT0();
        __syncthreads();
    }

    // ---- epilogue (m16 = pos, n8 = oc) ----
    if (MODE == 0) {
#pragma unroll
        for (int i = 0; i < 7; i++) {
            int m0 = wMb * 112 + i * 16 + (lane >> 2);
#pragma unroll
            for (int t = 0; t < 2; t++) {
                int oc0 = ocb + warp * 16 + t * 8 + 2 * (lane & 3);
                float* p = &g_branch[xbase + oc0 * HWP];
                if (m0 < HWP) {
                    p[m0]       = acc[i][t][0];
                    p[HWP + m0] = acc[i][t][1];
                }
                if (m0 + 8 < HWP) {
                    p[m0 + 8]       = acc[i][t][2];
                    p[HWP + m0 + 8] = acc[i][t][3];
                }
            }
        }
    } else {
        float sc[2][2], sh[2][2];
#pragma unroll
        for (int t = 0; t < 2; t++) {
#pragma unroll
            for (int j = 0; j < 2; j++) {
                int oc = ocb + warp * 16 + t * 8 + 2 * (lane & 3) + j;
                float s = bn_gamma[oc] * rsqrtf(bn_var[oc] + 1e-5f);
                sc[t][j] = s;
                sh[t][j] = bn_beta[oc] - bn_mean[oc] * s;
            }
        }
#pragma unroll
        for (int i = 0; i < 7; i++) {
            int m0 = wMb * 112 + i * 16 + (lane >> 2);
#pragma unroll
            for (int t = 0; t < 2; t++) {
                int oc0 = ocb + warp * 16 + t * 8 + 2 * (lane & 3);
                float* p = &out[xbase + oc0 * HWP];
                if (m0 < HWP) {
                    p[m0]       = fmaxf(fmaf(acc[i][t][0], sc[t][0], sh[t][0]), 0.0f);
                    p[HWP + m0] = fmaxf(fmaf(acc[i][t][1], sc[t][1], sh[t][1]), 0.0f);
                }
                if (m0 + 8 < HWP) {
                    p[m0 + 8]       = fmaxf(fmaf(acc[i][t][2], sc[t][0], sh[t][0]), 0.0f);
                    p[HWP + m0 + 8] = fmaxf(fmaf(acc[i][t][3], sc[t][1], sh[t][1]), 0.0f);
                }
            }
        }
    }
}

// ---------------- launch ------------------------------------------------------
extern "C" void kernel_launch(void* const* d_in, const int* in_sizes, int n_in,
                              void* d_out, int out_size) {
    const float* x       = (const float*)d_in[0];
    const float* gc      = (const float*)d_in[1];
    const float* boxes   = (const float*)d_in[2];
    const int*   classes = (const int*)  d_in[3];
    const float* Wc3     = (const float*)d_in[4];
    const float* Wc1     = (const float*)d_in[5];
    const float* Wt3     = (const float*)d_in[6];
    const float* Wt1     = (const float*)d_in[7];
    const float* Wf3     = (const float*)d_in[8];
    const float* Wf1     = (const float*)d_in[9];
    const float* bg      = (const float*)d_in[10];
    const float* bb      = (const float*)d_in[11];
    const float* bm      = (const float*)d_in[12];
    const float* bv      = (const float*)d_in[13];
    float* out = (float*)d_out;

    static bool attr_done = false;
    if (!attr_done) {
        cudaFuncSetAttribute(conv_mma<0>,
            cudaFuncAttributeMaxDynamicSharedMemorySize, SMEM_BYTES);
        cudaFuncSetAttribute(conv_mma<1>,
            cudaFuncAttributeMaxDynamicSharedMemorySize, SMEM_BYTES);
        attr_done = true;
    }

    mask_kernel<<<2, 256>>>(boxes);
    combine_kernel<<<dim3(72, 4, 3), 256>>>(Wc3, Wc1, Wt3, Wt1, Wf3, Wf1);
    conv_mma<0><<<dim3(4, NN), 256, SMEM_BYTES>>>(x, gc, classes, bg, bb, bm, bv, nullptr);
    conv_mma<1><<<dim3(4, NN), 256, SMEM_BYTES>>>(x, gc, classes, bg, bb, bm, bv, out);
}